// round 9
// baseline (speedup 1.0000x reference)
#include <cuda_runtime.h>
#include <cuda_bf16.h>
#include <cstdint>
#include <math.h>

#define BATCH 64
#define NN    1024
#define DD    16
#define THREADS 256

#define MROWS 64             // rows per CTA (4 row-groups x 16 rows; K split across warp halves)
#define KHALF 512            // K per warp group
#define SLAB  16             // k per pipeline step
#define NS    (KHALF / SLAB) // 32 steps

#define APITCH 48            // A tile row pitch bytes (16B-aligned, conflict-free ldmatrix)
#define BPITCH 48            // B tile row pitch bytes

// smem byte offsets (dynamic)
#define SM_B    0                      // 1024 x 48 = 49152
#define SM_A    49152                  // 8 warps x 16 x 48 = 6144
#define SM_DEG  55296                  // 2 halves x 64 rows floats = 512
#define SM_RED  55808                  // 24 floats = 96
#define SM_TOTAL 55936

__device__ float g_part[BATCH][NN / MROWS];   // per-CTA loss partials
__device__ int   g_cnt[BATCH];                // arrival counters (reset by finalizer)

// ---------------- helpers ----------------
__device__ __forceinline__ unsigned smem_u32(const void* p) {
    unsigned a;
    asm("{ .reg .u64 t; cvta.to.shared.u64 t, %1; cvt.u32.u64 %0, t; }" : "=r"(a) : "l"(p));
    return a;
}
__device__ __forceinline__ unsigned long long pk2(float a, float b) {
    unsigned long long r;
    asm("mov.b64 %0, {%1, %2};" : "=l"(r) : "f"(a), "f"(b));
    return r;
}
__device__ __forceinline__ void upk2(unsigned long long v, float& a, float& b) {
    asm("mov.b64 {%0, %1}, %2;" : "=f"(a), "=f"(b) : "l"(v));
}
__device__ __forceinline__ unsigned long long fma2(unsigned long long a,
                                                   unsigned long long b,
                                                   unsigned long long c) {
    unsigned long long d;
    asm("fma.rn.f32x2 %0, %1, %2, %3;" : "=l"(d) : "l"(a), "l"(b), "l"(c));
    return d;
}
__device__ __forceinline__ unsigned cvt_bf16x2(float lo, float hi) {
    unsigned r;  // memory layout: [lo, hi]
    asm("cvt.rn.satfinite.bf16x2.f32 %0, %1, %2;" : "=r"(r) : "f"(hi), "f"(lo));
    return r;
}
__device__ __forceinline__ unsigned long long pack4(float4 v) {
    unsigned h0 = cvt_bf16x2(v.x, v.y);
    unsigned h1 = cvt_bf16x2(v.z, v.w);
    return (unsigned long long)h0 | ((unsigned long long)h1 << 32);
}
__device__ __forceinline__ void ldsm4(unsigned* r, unsigned a) {
    asm volatile("ldmatrix.sync.aligned.m8n8.x4.shared.b16 {%0,%1,%2,%3}, [%4];"
                 : "=r"(r[0]), "=r"(r[1]), "=r"(r[2]), "=r"(r[3]) : "r"(a) : "memory");
}
__device__ __forceinline__ void ldsm4t(unsigned* r, unsigned a) {
    asm volatile("ldmatrix.sync.aligned.m8n8.x4.trans.shared.b16 {%0,%1,%2,%3}, [%4];"
                 : "=r"(r[0]), "=r"(r[1]), "=r"(r[2]), "=r"(r[3]) : "r"(a) : "memory");
}
__device__ __forceinline__ void mma_bf16(float* c, const unsigned* a,
                                         unsigned b0, unsigned b1) {
    asm volatile(
        "mma.sync.aligned.m16n8k16.row.col.f32.bf16.bf16.f32 "
        "{%0,%1,%2,%3}, {%4,%5,%6,%7}, {%8,%9}, {%0,%1,%2,%3};"
        : "+f"(c[0]), "+f"(c[1]), "+f"(c[2]), "+f"(c[3])
        : "r"(a[0]), "r"(a[1]), "r"(a[2]), "r"(a[3]), "r"(b0), "r"(b1));
}

__global__ void __launch_bounds__(THREADS, 4)
graph_loss_main(const float* __restrict__ A, const float* __restrict__ Fm,
                float* __restrict__ out) {
    extern __shared__ __align__(128) unsigned char smem[];
    unsigned char* sB   = smem + SM_B;
    unsigned char* sA   = smem + SM_A;
    float*         sDeg = (float*)(smem + SM_DEG);
    float*         sRed = (float*)(smem + SM_RED);

    const int rb   = blockIdx.x;           // 0..15
    const int b    = blockIdx.z;
    const int n0   = rb * MROWS;
    const int tid  = threadIdx.x;
    const int wid  = tid >> 5;
    const int lane = tid & 31;
    const int h    = wid >> 2;             // K half of this warp
    const int wg   = wid & 3;              // row group (16 rows)

    // ---- stage full F[b] into sB as bf16 [k][16] (48B pitch) ----
    {
        const float4* Fh = (const float4*)(Fm + (size_t)b * NN * DD);
        #pragma unroll
        for (int i = 0; i < (NN * DD / 4) / THREADS; i++) {
            int idx = tid + i * THREADS;       // 0..4095
            int k = idx >> 2, c4 = idx & 3;
            float4 v = Fh[idx];
            *(unsigned long long*)(sB + k * BPITCH + c4 * 8) = pack4(v);
        }
    }
    __syncthreads();

    // ---- per-warp setup ----
    unsigned char* myA = sA + wid * (16 * APITCH);
    const int r8 = lane >> 2;          // 0..7
    const int c4 = lane & 3;           // float4 index within 16-float slab row
    const float* Ap = A + ((size_t)b * NN + n0 + wg * 16 + r8) * NN
                        + (size_t)h * KHALF + c4 * 4;
    const size_t ROW8 = (size_t)8 * NN;

    unsigned char* sts0 = myA + r8 * APITCH + c4 * 8;
    unsigned char* sts1 = myA + (r8 + 8) * APITCH + c4 * 8;
    const unsigned ldmA = smem_u32(myA) + (lane & 15) * APITCH + (lane >> 4) * 16;
    const unsigned ldmB = smem_u32(sB) + (h * KHALF) * BPITCH
                          + (lane & 15) * BPITCH + (lane >> 4) * 16;

    float c0[4] = {0, 0, 0, 0};   // cols 0-7
    float c1[4] = {0, 0, 0, 0};   // cols 8-15
    float c2[4] = {0, 0, 0, 0};   // ones block (col 16 = deg)
    unsigned long long ss2 = 0ull;
    const unsigned bones = (lane < 4) ? 0x3F803F80u : 0u;

    float4 p0a = *(const float4*)(Ap);
    float4 p0b = *(const float4*)(Ap + ROW8);
    float4 p1a = *(const float4*)(Ap + SLAB);
    float4 p1b = *(const float4*)(Ap + ROW8 + SLAB);

    #pragma unroll 1
    for (int m = 0; m < NS / 2; m++) {
        {
            const int s = 2 * m;
            ss2 = fma2(pk2(p0a.x, p0a.y), pk2(p0a.x, p0a.y), ss2);
            ss2 = fma2(pk2(p0a.z, p0a.w), pk2(p0a.z, p0a.w), ss2);
            ss2 = fma2(pk2(p0b.x, p0b.y), pk2(p0b.x, p0b.y), ss2);
            ss2 = fma2(pk2(p0b.z, p0b.w), pk2(p0b.z, p0b.w), ss2);
            *(unsigned long long*)sts0 = pack4(p0a);
            *(unsigned long long*)sts1 = pack4(p0b);
            if (s + 2 < NS) {
                p0a = *(const float4*)(Ap + (s + 2) * SLAB);
                p0b = *(const float4*)(Ap + ROW8 + (s + 2) * SLAB);
            }
            unsigned af[4], bf[4];
            ldsm4(af, ldmA);
            ldsm4t(bf, ldmB + s * (SLAB * BPITCH));
            mma_bf16(c0, af, bf[0], bf[1]);
            mma_bf16(c1, af, bf[2], bf[3]);
            mma_bf16(c2, af, bones, bones);
        }
        {
            const int s = 2 * m + 1;
            ss2 = fma2(pk2(p1a.x, p1a.y), pk2(p1a.x, p1a.y), ss2);
            ss2 = fma2(pk2(p1a.z, p1a.w), pk2(p1a.z, p1a.w), ss2);
            ss2 = fma2(pk2(p1b.x, p1b.y), pk2(p1b.x, p1b.y), ss2);
            ss2 = fma2(pk2(p1b.z, p1b.w), pk2(p1b.z, p1b.w), ss2);
            *(unsigned long long*)sts0 = pack4(p1a);
            *(unsigned long long*)sts1 = pack4(p1b);
            if (s + 2 < NS) {
                p1a = *(const float4*)(Ap + (s + 2) * SLAB);
                p1b = *(const float4*)(Ap + ROW8 + (s + 2) * SLAB);
            }
            unsigned af[4], bf[4];
            ldsm4(af, ldmA);
            ldsm4t(bf, ldmB + s * (SLAB * BPITCH));
            mma_bf16(c0, af, bf[0], bf[1]);
            mma_bf16(c1, af, bf[2], bf[3]);
            mma_bf16(c2, af, bones, bones);
        }
    }

    // ---- epilogue ----
    // C frag: cX[0]=(r1, 2q), cX[1]=(r1, 2q+1), cX[2]=(r1+8, 2q), cX[3]=(r1+8, 2q+1)
    const int q  = lane & 3;
    const int r1 = lane >> 2;                  // 0..7
    const int lr1 = wg * 16 + r1;              // CTA-local rows
    const int lr2 = lr1 + 8;
    const int nrow1 = n0 + lr1;
    const int nrow2 = n0 + lr2;
    const float* F1 = Fm + ((size_t)b * NN + nrow1) * DD;
    const float* F2 = Fm + ((size_t)b * NN + nrow2) * DD;
    float2 fa1 = *(const float2*)(F1 + 2 * q);
    float2 fb1 = *(const float2*)(F1 + 8 + 2 * q);
    float2 fa2 = *(const float2*)(F2 + 2 * q);
    float2 fb2 = *(const float2*)(F2 + 8 + 2 * q);

    float dot1 = c0[0] * fa1.x + c0[1] * fa1.y + c1[0] * fb1.x + c1[1] * fb1.y;
    float dot2 = c0[2] * fa2.x + c0[3] * fa2.y + c1[2] * fb2.x + c1[3] * fb2.y;
    float nrm1 = fa1.x * fa1.x + fa1.y * fa1.y + fb1.x * fb1.x + fb1.y * fb1.y;
    float nrm2 = fa2.x * fa2.x + fa2.y * fa2.y + fb2.x * fb2.x + fb2.y * fb2.y;

    #pragma unroll
    for (int o = 1; o <= 2; o <<= 1) {
        dot1 += __shfl_xor_sync(0xFFFFFFFFu, dot1, o);
        dot2 += __shfl_xor_sync(0xFFFFFFFFu, dot2, o);
        nrm1 += __shfl_xor_sync(0xFFFFFFFFu, nrm1, o);
        nrm2 += __shfl_xor_sync(0xFFFFFFFFu, nrm2, o);
    }

    float v = 0.0f;
    if (q == 0) {
        float deg1 = c2[0], deg2 = c2[2];      // this half's partial degrees
        sDeg[h * MROWS + lr1] = deg1;
        sDeg[h * MROWS + lr2] = deg2;
        v = (deg1 * nrm1 - dot1) + (deg2 * nrm2 - dot2);
    }
    __syncthreads();

    float lg = 0.0f;
    if (h == 0 && q == 0) {
        float d1 = sDeg[lr1] + sDeg[MROWS + lr1];
        float d2 = sDeg[lr2] + sDeg[MROWS + lr2];
        lg = logf(d1 + 1e-12f) + logf(d2 + 1e-12f);
    }

    float ssa, ssb;
    upk2(ss2, ssa, ssb);
    float ssv = ssa + ssb;
    #pragma unroll
    for (int o = 16; o > 0; o >>= 1) {
        v   += __shfl_down_sync(0xFFFFFFFFu, v, o);
        ssv += __shfl_down_sync(0xFFFFFFFFu, ssv, o);
        lg  += __shfl_down_sync(0xFFFFFFFFu, lg, o);
    }
    if (lane == 0) { sRed[wid] = ssv; sRed[8 + wid] = v; sRed[16 + wid] = lg; }
    __syncthreads();

    if (tid == 0) {
        float ss = 0.0f, sm = 0.0f, lgs = 0.0f;
        #pragma unroll
        for (int k = 0; k < 8; k++) { ss += sRed[k]; sm += sRed[8 + k]; lgs += sRed[16 + k]; }
        const float invN2 = 1.0f / ((float)NN * (float)NN);
        g_part[b][rb] = (0.2f * sm + 0.1f * ss) * invN2 - 0.1f * lgs / (float)NN;
        __threadfence();
        int old = atomicAdd(&g_cnt[b], 1);
        if (old == (NN / MROWS) - 1) {         // last CTA for this batch
            __threadfence();
            float tot = 0.0f;
            #pragma unroll
            for (int k = 0; k < NN / MROWS; k++) tot += g_part[b][k];
            out[b] = tot;
            g_cnt[b] = 0;                      // reset for next graph replay
        }
    }
}

extern "C" void kernel_launch(void* const* d_in, const int* in_sizes, int n_in,
                              void* d_out, int out_size) {
    const float* A  = (const float*)d_in[0];   // [64,1024,1024]
    const float* Fm = (const float*)d_in[1];   // [64,1024,16]
    float* out      = (float*)d_out;           // [64]

    cudaFuncSetAttribute(graph_loss_main,
                         cudaFuncAttributeMaxDynamicSharedMemorySize, SM_TOTAL);

    dim3 grid(NN / MROWS, 1, BATCH);           // (16, 1, 64) = 1024 CTAs
    graph_loss_main<<<grid, THREADS, SM_TOTAL>>>(A, Fm, out);
}

// round 11
// speedup vs baseline: 1.3226x; 1.3226x over previous
#include <cuda_runtime.h>
#include <cuda_bf16.h>
#include <cstdint>
#include <math.h>

#define BATCH 64
#define NN    1024
#define DD    16
#define THREADS 256

#define MROWS 128            // rows per CTA (8 warps x 16 rows)
#define KH    512            // K columns per CTA (half of N)
#define SLAB  16             // k per pipeline step
#define NS    (KH / SLAB)    // 32 steps

#define APITCH 48            // A tile row pitch bytes (16B-aligned, conflict-free ldmatrix)
#define BPITCH 48            // B tile row pitch bytes

#define CTAS_PER_B (2 * (NN / MROWS))   // 16

__device__ float g_deg[BATCH][NN][2];           // per-(b,n) degree halves
__device__ float g_part[BATCH][2][NN / MROWS];  // per-CTA loss partials
__device__ int   g_cnt[BATCH];                  // arrival counters (reset by finalizer)

// ---------------- helpers ----------------
__device__ __forceinline__ unsigned smem_u32(const void* p) {
    unsigned a;
    asm("{ .reg .u64 t; cvta.to.shared.u64 t, %1; cvt.u32.u64 %0, t; }" : "=r"(a) : "l"(p));
    return a;
}
__device__ __forceinline__ unsigned long long pk2(float a, float b) {
    unsigned long long r;
    asm("mov.b64 %0, {%1, %2};" : "=l"(r) : "f"(a), "f"(b));
    return r;
}
__device__ __forceinline__ void upk2(unsigned long long v, float& a, float& b) {
    asm("mov.b64 {%0, %1}, %2;" : "=f"(a), "=f"(b) : "l"(v));
}
__device__ __forceinline__ unsigned long long fma2(unsigned long long a,
                                                   unsigned long long b,
                                                   unsigned long long c) {
    unsigned long long d;
    asm("fma.rn.f32x2 %0, %1, %2, %3;" : "=l"(d) : "l"(a), "l"(b), "l"(c));
    return d;
}
__device__ __forceinline__ unsigned cvt_bf16x2(float lo, float hi) {
    unsigned r;  // memory layout: [lo, hi]
    asm("cvt.rn.satfinite.bf16x2.f32 %0, %1, %2;" : "=r"(r) : "f"(hi), "f"(lo));
    return r;
}
__device__ __forceinline__ unsigned long long pack4(float4 v) {
    unsigned h0 = cvt_bf16x2(v.x, v.y);
    unsigned h1 = cvt_bf16x2(v.z, v.w);
    return (unsigned long long)h0 | ((unsigned long long)h1 << 32);
}
__device__ __forceinline__ void ldsm4(unsigned* r, unsigned a) {
    asm volatile("ldmatrix.sync.aligned.m8n8.x4.shared.b16 {%0,%1,%2,%3}, [%4];"
                 : "=r"(r[0]), "=r"(r[1]), "=r"(r[2]), "=r"(r[3]) : "r"(a) : "memory");
}
__device__ __forceinline__ void ldsm4t(unsigned* r, unsigned a) {
    asm volatile("ldmatrix.sync.aligned.m8n8.x4.trans.shared.b16 {%0,%1,%2,%3}, [%4];"
                 : "=r"(r[0]), "=r"(r[1]), "=r"(r[2]), "=r"(r[3]) : "r"(a) : "memory");
}
__device__ __forceinline__ void mma_bf16(float* c, const unsigned* a,
                                         unsigned b0, unsigned b1) {
    asm volatile(
        "mma.sync.aligned.m16n8k16.row.col.f32.bf16.bf16.f32 "
        "{%0,%1,%2,%3}, {%4,%5,%6,%7}, {%8,%9}, {%0,%1,%2,%3};"
        : "+f"(c[0]), "+f"(c[1]), "+f"(c[2]), "+f"(c[3])
        : "r"(a[0]), "r"(a[1]), "r"(a[2]), "r"(a[3]), "r"(b0), "r"(b1));
}

__global__ void __launch_bounds__(THREADS, 4)
graph_loss_main(const float* __restrict__ A, const float* __restrict__ Fm,
                float* __restrict__ out) {
    __shared__ __align__(128) unsigned char sB[KH * BPITCH];         // F half: [k][16 bf16]
    __shared__ __align__(128) unsigned char sA[8 * 16 * APITCH];     // per-warp A tiles
    __shared__ float sRed[16];
    __shared__ int   sLast;

    const int rb   = blockIdx.x;
    const int half = blockIdx.y;
    const int b    = blockIdx.z;
    const int n0   = rb * MROWS;
    const int tid  = threadIdx.x;
    const int wid  = tid >> 5;
    const int lane = tid & 31;

    // ---- stage F-half into sB as bf16 [k][16] (48B pitch) ----
    {
        const float4* Fh = (const float4*)(Fm + ((size_t)b * NN + (size_t)half * KH) * DD);
        #pragma unroll
        for (int i = 0; i < (KH * DD / 4) / THREADS; i++) {
            int idx = tid + i * THREADS;       // 0..2047
            int k = idx >> 2, c4 = idx & 3;
            float4 v = Fh[idx];
            *(unsigned long long*)(sB + k * BPITCH + c4 * 8) = pack4(v);
        }
    }
    __syncthreads();

    // ---- per-warp setup ----
    unsigned char* myA = sA + wid * (16 * APITCH);
    const int r8 = lane >> 2;          // 0..7
    const int c4 = lane & 3;           // float4 index within 16-float slab row
    const float* Ap = A + ((size_t)b * NN + n0 + wid * 16 + r8) * NN
                        + (size_t)half * KH + c4 * 4;
    const size_t ROW8 = (size_t)8 * NN;

    unsigned char* sts0 = myA + r8 * APITCH + c4 * 8;
    unsigned char* sts1 = myA + (r8 + 8) * APITCH + c4 * 8;
    const unsigned ldmA = smem_u32(myA) + (lane & 15) * APITCH + (lane >> 4) * 16;
    const unsigned ldmB = smem_u32(sB) + (lane & 15) * BPITCH + (lane >> 4) * 16;

    float c0[4] = {0, 0, 0, 0};   // cols 0-7
    float c1[4] = {0, 0, 0, 0};   // cols 8-15
    float c2[4] = {0, 0, 0, 0};   // ones block (col 16 = deg)
    unsigned long long ss2 = 0ull;
    const unsigned bones = (lane < 4) ? 0x3F803F80u : 0u;  // ones column frag

    float4 p0a = *(const float4*)(Ap);
    float4 p0b = *(const float4*)(Ap + ROW8);
    float4 p1a = *(const float4*)(Ap + SLAB);
    float4 p1b = *(const float4*)(Ap + ROW8 + SLAB);

    #pragma unroll 1
    for (int m = 0; m < NS / 2; m++) {
        {
            const int s = 2 * m;
            ss2 = fma2(pk2(p0a.x, p0a.y), pk2(p0a.x, p0a.y), ss2);
            ss2 = fma2(pk2(p0a.z, p0a.w), pk2(p0a.z, p0a.w), ss2);
            ss2 = fma2(pk2(p0b.x, p0b.y), pk2(p0b.x, p0b.y), ss2);
            ss2 = fma2(pk2(p0b.z, p0b.w), pk2(p0b.z, p0b.w), ss2);
            *(unsigned long long*)sts0 = pack4(p0a);
            *(unsigned long long*)sts1 = pack4(p0b);
            if (s + 2 < NS) {
                p0a = *(const float4*)(Ap + (s + 2) * SLAB);
                p0b = *(const float4*)(Ap + ROW8 + (s + 2) * SLAB);
            }
            unsigned af[4], bf[4];
            ldsm4(af, ldmA);
            ldsm4t(bf, ldmB + s * (SLAB * BPITCH));
            mma_bf16(c0, af, bf[0], bf[1]);
            mma_bf16(c1, af, bf[2], bf[3]);
            mma_bf16(c2, af, bones, bones);
        }
        {
            const int s = 2 * m + 1;
            ss2 = fma2(pk2(p1a.x, p1a.y), pk2(p1a.x, p1a.y), ss2);
            ss2 = fma2(pk2(p1a.z, p1a.w), pk2(p1a.z, p1a.w), ss2);
            ss2 = fma2(pk2(p1b.x, p1b.y), pk2(p1b.x, p1b.y), ss2);
            ss2 = fma2(pk2(p1b.z, p1b.w), pk2(p1b.z, p1b.w), ss2);
            *(unsigned long long*)sts0 = pack4(p1a);
            *(unsigned long long*)sts1 = pack4(p1b);
            if (s + 2 < NS) {
                p1a = *(const float4*)(Ap + (s + 2) * SLAB);
                p1b = *(const float4*)(Ap + ROW8 + (s + 2) * SLAB);
            }
            unsigned af[4], bf[4];
            ldsm4(af, ldmA);
            ldsm4t(bf, ldmB + s * (SLAB * BPITCH));
            mma_bf16(c0, af, bf[0], bf[1]);
            mma_bf16(c1, af, bf[2], bf[3]);
            mma_bf16(c2, af, bones, bones);
        }
    }

    // ---- epilogue ----
    // C frag: cX[0]=(r1, 2q), cX[1]=(r1, 2q+1), cX[2]=(r1+8, 2q), cX[3]=(r1+8, 2q+1)
    const int q  = lane & 3;
    const int r1 = lane >> 2;                  // 0..7
    const int nrow1 = n0 + wid * 16 + r1;
    const int nrow2 = nrow1 + 8;
    const float* F1 = Fm + ((size_t)b * NN + nrow1) * DD;
    const float* F2 = Fm + ((size_t)b * NN + nrow2) * DD;
    float2 fa1 = *(const float2*)(F1 + 2 * q);
    float2 fb1 = *(const float2*)(F1 + 8 + 2 * q);
    float2 fa2 = *(const float2*)(F2 + 2 * q);
    float2 fb2 = *(const float2*)(F2 + 8 + 2 * q);

    float dot1 = c0[0] * fa1.x + c0[1] * fa1.y + c1[0] * fb1.x + c1[1] * fb1.y;
    float dot2 = c0[2] * fa2.x + c0[3] * fa2.y + c1[2] * fb2.x + c1[3] * fb2.y;
    float nrm1 = fa1.x * fa1.x + fa1.y * fa1.y + fb1.x * fb1.x + fb1.y * fb1.y;
    float nrm2 = fa2.x * fa2.x + fa2.y * fa2.y + fb2.x * fb2.x + fb2.y * fb2.y;

    #pragma unroll
    for (int o = 1; o <= 2; o <<= 1) {
        dot1 += __shfl_xor_sync(0xFFFFFFFFu, dot1, o);
        dot2 += __shfl_xor_sync(0xFFFFFFFFu, dot2, o);
        nrm1 += __shfl_xor_sync(0xFFFFFFFFu, nrm1, o);
        nrm2 += __shfl_xor_sync(0xFFFFFFFFu, nrm2, o);
    }

    float v = 0.0f;
    if (q == 0) {
        float deg1 = c2[0], deg2 = c2[2];      // col 16 of ones-block
        g_deg[b][nrow1][half] = deg1;
        g_deg[b][nrow2][half] = deg2;
        v = (deg1 * nrm1 - dot1) + (deg2 * nrm2 - dot2);
    }
    float ssa, ssb;
    upk2(ss2, ssa, ssb);
    float ssv = ssa + ssb;
    #pragma unroll
    for (int o = 16; o > 0; o >>= 1) {
        v   += __shfl_down_sync(0xFFFFFFFFu, v, o);
        ssv += __shfl_down_sync(0xFFFFFFFFu, ssv, o);
    }
    if (lane == 0) { sRed[wid] = ssv; sRed[8 + wid] = v; }
    __syncthreads();
    if (tid == 0) {
        float ss = 0.0f, sm = 0.0f;
        #pragma unroll
        for (int k = 0; k < 8; k++) { ss += sRed[k]; sm += sRed[8 + k]; }
        const float invN2 = 1.0f / ((float)NN * (float)NN);
        g_part[b][half][rb] = (0.2f * sm + 0.1f * ss) * invN2;
        __threadfence();                               // publish g_part + g_deg
        int old = atomicAdd(&g_cnt[b], 1);
        sLast = (old == CTAS_PER_B - 1) ? 1 : 0;
    }
    __syncthreads();

    // ---- fused finalize: last-arriving CTA of this batch does the log term ----
    if (sLast) {
        __threadfence();                               // acquire other CTAs' writes
        float s = 0.0f;
        #pragma unroll
        for (int i = 0; i < NN / THREADS; i++) {
            int n = tid + i * THREADS;
            float2 dh = *(const float2*)&g_deg[b][n][0];
            s += logf(dh.x + dh.y + 1e-12f);
        }
        #pragma unroll
        for (int o = 16; o > 0; o >>= 1)
            s += __shfl_down_sync(0xFFFFFFFFu, s, o);
        if (lane == 0) sRed[wid] = s;
        __syncthreads();
        if (tid == 0) {
            float lg = 0.0f;
            #pragma unroll
            for (int k = 0; k < 8; k++) lg += sRed[k];
            float ps = 0.0f;
            #pragma unroll
            for (int hh = 0; hh < 2; hh++)
                #pragma unroll
                for (int rbl = 0; rbl < NN / MROWS; rbl++) ps += g_part[b][hh][rbl];
            out[b] = ps - 0.1f * lg / (float)NN;
            g_cnt[b] = 0;                              // reset for next graph replay
        }
    }
}

extern "C" void kernel_launch(void* const* d_in, const int* in_sizes, int n_in,
                              void* d_out, int out_size) {
    const float* A  = (const float*)d_in[0];   // [64,1024,1024]
    const float* Fm = (const float*)d_in[1];   // [64,1024,16]
    float* out      = (float*)d_out;           // [64]

    dim3 grid(NN / MROWS, 2, BATCH);           // (8, 2, 64) = 1024 CTAs
    graph_loss_main<<<grid, THREADS>>>(A, Fm, out);
}